// round 12
// baseline (speedup 1.0000x reference)
#include <cuda_runtime.h>
#include <cstdint>

#define FULL_MASK 0xFFFFFFFFu
#define TAGS 32
#define START 30
#define STOP 31

typedef unsigned long long ull;

__device__ float g_alpha[2048 * TAGS];
__device__ float g_beta [2048 * TAGS];
__device__ float g_lsA[2048];
__device__ float g_lsB[2048];
__device__ float g_partial[2048];
__device__ int   g_order[2048];
__device__ int   g_count = 0;

// ---------- helpers ----------
__device__ __forceinline__ uint32_t cvt_tf32(float x) {
    uint32_t r; asm("cvt.rna.tf32.f32 %0, %1;" : "=r"(r) : "f"(x)); return r;
}
__device__ __forceinline__ ull pack_u32(uint32_t lo, uint32_t hi) {
    ull r; asm("mov.b64 %0, {%1, %2};" : "=l"(r) : "r"(lo), "r"(hi)); return r;
}
__device__ __forceinline__ void sts64(uint32_t addr, ull v) {
    asm volatile("st.shared.b64 [%0], %1;" :: "r"(addr), "l"(v));
}
__device__ __forceinline__ uint32_t lds_u32(uint32_t addr) {
    uint32_t v; asm volatile("ld.shared.b32 %0, [%1];" : "=r"(v) : "r"(addr)); return v;
}
__device__ __forceinline__ uint32_t smem_u32(const void* p) {
    uint32_t a;
    asm("{ .reg .u64 t; cvta.to.shared.u64 t, %1; cvt.u32.u64 %0, t; }" : "=r"(a) : "l"(p));
    return a;
}
__device__ __forceinline__ void mma_tf32(float d[4],
    uint32_t a0, uint32_t a1, uint32_t a2, uint32_t a3, uint32_t b0, uint32_t b1) {
    asm volatile(
        "mma.sync.aligned.m16n8k8.row.col.f32.tf32.tf32.f32 "
        "{%0,%1,%2,%3}, {%4,%5,%6,%7}, {%8,%9}, {%0,%1,%2,%3};"
        : "+f"(d[0]), "+f"(d[1]), "+f"(d[2]), "+f"(d[3])
        : "r"(a0), "r"(a1), "r"(a2), "r"(a3), "r"(b0), "r"(b1));
}

// ---------- counting sort by descending length ----------
__global__ void sort_kernel(const int* __restrict__ lens, int B, int L)
{
    __shared__ int scan[1032];
    __shared__ int offs[1032];
    int tid = threadIdx.x;
    int nb = L + 1;
    if (L > 1023) {
        for (int b = tid; b < B; b += blockDim.x) g_order[b] = b;
        return;
    }
    for (int i = tid; i < nb; i += blockDim.x) scan[i] = 0;
    __syncthreads();
    for (int b = tid; b < B; b += blockDim.x)
        atomicAdd(&scan[L - lens[b]], 1);
    __syncthreads();
    for (int off = 1; off < nb; off <<= 1) {
        int v = 0;
        if (tid < nb && tid >= off) v = scan[tid - off];
        __syncthreads();
        if (tid < nb && tid >= off) scan[tid] += v;
        __syncthreads();
    }
    if (tid < nb) offs[tid] = (tid == 0) ? 0 : scan[tid - 1];
    __syncthreads();
    for (int b = tid; b < B; b += blockDim.x) {
        int pos = atomicAdd(&offs[L - lens[b]], 1);
        g_order[pos] = b;
    }
}

// ---------- main scan: one warp = 16 batches, fwd OR bwd direction ----------
// State P(16x32). Step: P <- (P . E) (.) exp(F_t) via 16x mma.m16n8k8.tf32.
// Rows snapshot alpha_m / beta_m to global at their per-row split step.
__global__ void __launch_bounds__(32, 8)
crf_scan_kernel(const float* __restrict__ feats,
                const float* __restrict__ trans,
                const int*   __restrict__ lens,
                int B, int L)
{
    __shared__ __align__(16) float Ps[16][36];   // padded stride 36

    int lane = threadIdx.x;
    int g    = blockIdx.x >> 1;
    bool isF = (blockIdx.x & 1) == 0;
    int q    = lane & 3;         // threadID in quad
    int gid  = lane >> 2;        // row group (rows gid, gid+8)

    int i0 = min(g * 16 + gid,     B - 1);
    int i1 = min(g * 16 + gid + 8, B - 1);
    int bid0 = g_order[i0], bid1 = g_order[i1];
    int len0 = lens[bid0], len1 = lens[bid1];
    int m0 = (len0 - 1) >> 1, m1 = (len1 - 1) >> 1;

    int lenmax = __shfl_sync(FULL_MASK, len0, 0);   // rows sorted desc: row 0 longest
    int mW = (lenmax - 1) >> 1;
    int stepsW = isF ? mW : (lenmax - 1 - mW);
    int snap0  = isF ? m0 : (len0 - 1 - m0);
    int snap1  = isF ? m1 : (len1 - 1 - m1);

    const float* f0 = feats + (size_t)bid0 * L * TAGS;
    const float* f1 = feats + (size_t)bid1 * L * TAGS;

    // E fragments (constant all steps). fwd: B=E; bwd: B=E^T.
    uint32_t Bf[4][4][2];
#pragma unroll
    for (int kc = 0; kc < 4; ++kc)
#pragma unroll
        for (int nc = 0; nc < 4; ++nc) {
            int k0 = 8 * kc + q, k1 = k0 + 4, n = 8 * nc + gid;
            float e0, e1;
            if (isF) { e0 = __expf(trans[k0 * TAGS + n]); e1 = __expf(trans[k1 * TAGS + n]); }
            else     { e0 = __expf(trans[n * TAGS + k0]); e1 = __expf(trans[n * TAGS + k1]); }
            Bf[kc][nc][0] = cvt_tf32(e0);
            Bf[kc][nc][1] = cvt_tf32(e1);
        }

    // init D: fwd exp(alpha0), bwd exp(trans[:,STOP])
    float d[4][4];
#pragma unroll
    for (int nc = 0; nc < 4; ++nc) {
        int n = 8 * nc + 2 * q;
        if (isF) {
            d[nc][0] = __expf(trans[START * TAGS + n]     + f0[n]);
            d[nc][1] = __expf(trans[START * TAGS + n + 1] + f0[n + 1]);
            d[nc][2] = __expf(trans[START * TAGS + n]     + f1[n]);
            d[nc][3] = __expf(trans[START * TAGS + n + 1] + f1[n + 1]);
        } else {
            d[nc][0] = __expf(trans[n * TAGS + STOP]);
            d[nc][1] = __expf(trans[(n + 1) * TAGS + STOP]);
            d[nc][2] = d[nc][0];
            d[nc][3] = d[nc][1];
        }
    }
    float ls0 = 0.f, ls1 = 0.f;

    float* snapA = isF ? g_alpha : g_beta;
    float* snapL = isF ? g_lsA   : g_lsB;

    // rows with zero steps snapshot their initial state
    if (snap0 == 0) {
#pragma unroll
        for (int nc = 0; nc < 4; ++nc)
            *(float2*)&snapA[bid0 * TAGS + 8 * nc + 2 * q] = make_float2(d[nc][0], d[nc][1]);
        if (q == 0) snapL[bid0] = 0.f;
    }
    if (snap1 == 0) {
#pragma unroll
        for (int nc = 0; nc < 4; ++nc)
            *(float2*)&snapA[bid1 * TAGS + 8 * nc + 2 * q] = make_float2(d[nc][2], d[nc][3]);
        if (q == 0) snapL[bid1] = 0.f;
    }

    // feat ring (2 deep) + L2 prefetch ahead
    float2 rg0[8], rg1[8];
#pragma unroll
    for (int s = 0; s < 2; ++s) {
        int tt = 1 + s;
        int a0i = isF ? min(tt, m0) : max(len0 - tt, 0);
        int a1i = isF ? min(tt, m1) : max(len1 - tt, 0);
        float2* dst = s ? rg1 : rg0;
#pragma unroll
        for (int nc = 0; nc < 4; ++nc) {
            dst[nc]     = *(const float2*)(f0 + (size_t)a0i * TAGS + 8 * nc + 2 * q);
            dst[4 + nc] = *(const float2*)(f1 + (size_t)a1i * TAGS + 8 * nc + 2 * q);
        }
    }

    uint32_t ps = smem_u32(&Ps[0][0]);
    float sc0 = 1.f, rr0 = 1.f, lg0 = 0.f;
    float sc1 = 1.f, rr1 = 1.f, lg1 = 0.f;

    for (int t = 1; t <= stepsW; ++t) {
        // exp of current feats (ef[2j], ef[2j+1] = row(j>>2 ? 1:0), nc=j%4 pair)
        float ef[16];
#pragma unroll
        for (int j = 0; j < 8; ++j) {
            ef[2 * j]     = __expf(rg0[j].x);
            ef[2 * j + 1] = __expf(rg0[j].y);
        }
        // ring advance + prefetch
#pragma unroll
        for (int j = 0; j < 8; ++j) rg0[j] = rg1[j];
        {
            int t2 = t + 2;
            int a0i = isF ? min(t2, m0) : max(len0 - t2, 0);
            int a1i = isF ? min(t2, m1) : max(len1 - t2, 0);
#pragma unroll
            for (int nc = 0; nc < 4; ++nc) {
                rg1[nc]     = *(const float2*)(f0 + (size_t)a0i * TAGS + 8 * nc + 2 * q);
                rg1[4 + nc] = *(const float2*)(f1 + (size_t)a1i * TAGS + 8 * nc + 2 * q);
            }
            if (q == 0) {
                int p0 = isF ? min(t + 8, m0) : max(len0 - t - 8, 0);
                int p1 = isF ? min(t + 8, m1) : max(len1 - t - 8, 0);
                asm volatile("prefetch.global.L2 [%0];" :: "l"(f0 + (size_t)p0 * TAGS));
                asm volatile("prefetch.global.L2 [%0];" :: "l"(f1 + (size_t)p1 * TAGS));
            }
        }

        // store P tile (bwd pre-multiplies by exp(f))
        __syncwarp();
#pragma unroll
        for (int nc = 0; nc < 4; ++nc) {
            float x0 = d[nc][0], y0 = d[nc][1], x1 = d[nc][2], y1 = d[nc][3];
            if (!isF) {
                x0 *= ef[2 * nc];     y0 *= ef[2 * nc + 1];
                x1 *= ef[8 + 2 * nc]; y1 *= ef[8 + 2 * nc + 1];
            }
            sts64(ps + (uint32_t)(gid * 36       + 8 * nc + 2 * q) * 4, pack_u32(cvt_tf32(x0), cvt_tf32(y0)));
            sts64(ps + (uint32_t)((gid + 8) * 36 + 8 * nc + 2 * q) * 4, pack_u32(cvt_tf32(x1), cvt_tf32(y1)));
        }
        __syncwarp();

        // A fragments + 16 MMAs (4 n-chunks x 4 k-chunks)
        uint32_t a[4][4];
#pragma unroll
        for (int kc = 0; kc < 4; ++kc) {
            a[kc][0] = lds_u32(ps + (uint32_t)(gid * 36       + 8 * kc + q) * 4);
            a[kc][1] = lds_u32(ps + (uint32_t)((gid + 8) * 36 + 8 * kc + q) * 4);
            a[kc][2] = lds_u32(ps + (uint32_t)(gid * 36       + 8 * kc + q + 4) * 4);
            a[kc][3] = lds_u32(ps + (uint32_t)((gid + 8) * 36 + 8 * kc + q + 4) * 4);
        }
#pragma unroll
        for (int nc = 0; nc < 4; ++nc) {
            d[nc][0] = d[nc][1] = d[nc][2] = d[nc][3] = 0.f;
#pragma unroll
            for (int kc = 0; kc < 4; ++kc)
                mma_tf32(d[nc], a[kc][0], a[kc][1], a[kc][2], a[kc][3],
                         Bf[kc][nc][0], Bf[kc][nc][1]);
        }
        if (isF) {
#pragma unroll
            for (int nc = 0; nc < 4; ++nc) {
                d[nc][0] *= ef[2 * nc];     d[nc][1] *= ef[2 * nc + 1];
                d[nc][2] *= ef[8 + 2 * nc]; d[nc][3] *= ef[8 + 2 * nc + 1];
            }
        }

        // pipelined per-row renorm (stale scale = row's element 0; exact bookkeeping)
        int ph = t & 3;
        if (ph == 0) {
            sc0 = __shfl_sync(FULL_MASK, d[0][0], lane & ~3);
            sc1 = __shfl_sync(FULL_MASK, d[0][2], lane & ~3);
        } else if (ph == 1) {
            rr0 = __fdividef(1.f, sc0);  lg0 = __logf(sc0);
            rr1 = __fdividef(1.f, sc1);  lg1 = __logf(sc1);
        } else if (ph == 3) {
#pragma unroll
            for (int nc = 0; nc < 4; ++nc) {
                d[nc][0] *= rr0; d[nc][1] *= rr0;
                d[nc][2] *= rr1; d[nc][3] *= rr1;
            }
            ls0 += lg0; ls1 += lg1;
        }

        // per-row snapshots at the split point
        if (t == snap0) {
#pragma unroll
            for (int nc = 0; nc < 4; ++nc)
                *(float2*)&snapA[bid0 * TAGS + 8 * nc + 2 * q] = make_float2(d[nc][0], d[nc][1]);
            if (q == 0) snapL[bid0] = ls0;
        }
        if (t == snap1) {
#pragma unroll
            for (int nc = 0; nc < 4; ++nc)
                *(float2*)&snapA[bid1 * TAGS + 8 * nc + 2 * q] = make_float2(d[nc][2], d[nc][3]);
            if (q == 0) snapL[bid1] = ls1;
        }
    }
}

// ---------- combine: Z = <alpha_m, beta_m>, gold score, final reduction ----------
__global__ void __launch_bounds__(32, 16)
combine_kernel(const float* __restrict__ feats,
               const float* __restrict__ trans,
               const int*   __restrict__ tags,
               const int*   __restrict__ lens,
               float* __restrict__ out, int B, int L)
{
    int b = blockIdx.x;
    int lane = threadIdx.x;
    const float* fb = feats + (size_t)b * L * TAGS;
    const int*   tb = tags  + (size_t)b * L;
    int len = lens[b];

    float v = g_alpha[b * TAGS + lane] * g_beta[b * TAGS + lane];
#pragma unroll
    for (int o = 16; o; o >>= 1) v += __shfl_xor_sync(FULL_MASK, v, o);
    float fwd = g_lsA[b] + g_lsB[b] + __logf(v);

    float midsum = 0.f;
    for (int t = lane; t < len - 1; t += 32) {
        int u = tb[t], w = tb[t + 1];
        midsum += trans[u * TAGS + w] + fb[(t + 1) * TAGS + w];
    }
#pragma unroll
    for (int o = 16; o; o >>= 1) midsum += __shfl_xor_sync(FULL_MASK, midsum, o);

    if (lane == 0) {
        int tag0 = tb[0];
        int tend = tb[len - 1];
        float gold = trans[START * TAGS + tag0] + fb[tag0]
                   + trans[tend * TAGS + STOP] + midsum;
        g_partial[b] = fwd - gold;
    }

    __threadfence();
    int old = 0;
    if (lane == 0) old = atomicAdd(&g_count, 1);
    old = __shfl_sync(FULL_MASK, old, 0);
    if (old == B - 1) {
        __threadfence();
        double acc = 0.0;
        for (int i = lane; i < B; i += 32)
            acc += (double)((volatile float*)g_partial)[i];
#pragma unroll
        for (int o = 16; o; o >>= 1)
            acc += __shfl_xor_sync(FULL_MASK, acc, o);
        if (lane == 0) {
            out[0] = (float)acc;
            g_count = 0;   // reset for next graph replay
        }
    }
}

extern "C" void kernel_launch(void* const* d_in, const int* in_sizes, int n_in,
                              void* d_out, int out_size)
{
    const float* feats = (const float*)d_in[0];
    const float* trans = (const float*)d_in[1];
    const int*   tags  = (const int*)d_in[2];
    const int*   lens  = (const int*)d_in[3];
    float* out = (float*)d_out;

    int B = in_sizes[3];                  // word_seq_lens: (B,)
    int L = in_sizes[2] / B;              // tags: (B, L)

    int ngroups = (B + 15) / 16;
    sort_kernel<<<1, 1024>>>(lens, B, L);
    crf_scan_kernel<<<ngroups * 2, 32>>>(feats, trans, lens, B, L);
    combine_kernel<<<B, 32>>>(feats, trans, tags, lens, out, B, L);
}